// round 2
// baseline (speedup 1.0000x reference)
#include <cuda_runtime.h>
#include <cstdint>
#include <math_constants.h>

#define B_   8
#define C_   256
#define N_   4096
#define CQK  32

typedef unsigned long long u64;

// Scratch (device globals: allocation-free rule)
__device__ float g_q[(size_t)B_ * N_ * CQK];          // [b][n][32]
__device__ float g_k[(size_t)B_ * N_ * CQK];          // [b][n][32]
__device__ float g_v[(size_t)B_ * N_ * C_];           // [b][n][256]  (token-major)
__device__ float g_o[(size_t)B_ * N_ * C_];           // [b][n][256]  (token-major)

// ---------------- packed f32x2 helpers (FFMA2 path, sm_103a) ----------------
__device__ __forceinline__ void ffma2(u64& d, u64 a, u64 b) {
    asm("fma.rn.f32x2 %0, %1, %2, %0;" : "+l"(d) : "l"(a), "l"(b));
}
__device__ __forceinline__ u64 mul2(u64 a, u64 b) {
    u64 r; asm("mul.rn.f32x2 %0, %1, %2;" : "=l"(r) : "l"(a), "l"(b)); return r;
}
__device__ __forceinline__ u64 pack2(float v) {
    u64 r; unsigned u = __float_as_uint(v);
    asm("mov.b64 %0, {%1, %1};" : "=l"(r) : "r"(u)); return r;
}
__device__ __forceinline__ float2 unpack2(u64 v) {
    float2 r; asm("mov.b64 {%0, %1}, %2;" : "=f"(r.x), "=f"(r.y) : "l"(v)); return r;
}

// ---------------- Kernel 1: q/k/v projections ----------------
// grid (N/64, B), 256 threads, dynamic smem 64KB: x tile [256][64]
__global__ __launch_bounds__(256) void proj_kernel(
    const float* __restrict__ x,
    const float* __restrict__ Wq, const float* __restrict__ bq,
    const float* __restrict__ Wk, const float* __restrict__ bk,
    const float* __restrict__ Wv, const float* __restrict__ bv)
{
    extern __shared__ float xs[];               // [256][64]
    float4* xs4 = (float4*)xs;
    const int b   = blockIdx.y;
    const int n0  = blockIdx.x * 64;
    const int tid = threadIdx.x;
    const int tx  = tid & 15;                   // col group: cols tx*4..tx*4+3
    const int ty  = tid >> 4;                   // row group 0..15

    // stage x tile [C=256][64] (coalesced float4 loads)
    const float4* x4 = (const float4*)(x + ((size_t)b * C_) * N_ + n0);
    for (int i = tid; i < C_ * 16; i += 256) {
        int c = i >> 4, t4 = i & 15;
        xs4[c * 16 + t4] = x4[(size_t)c * (N_ / 4) + t4];
    }
    __syncthreads();

    #pragma unroll 1
    for (int rb = 0; rb < 5; rb++) {
        const float* W; const float* bias; int r0;
        if (rb == 0) {
            if (ty < 8) { W = Wq; bias = bq; r0 = ty * 4; }
            else        { W = Wk; bias = bk; r0 = (ty - 8) * 4; }
        } else {
            W = Wv; bias = bv; r0 = (rb - 1) * 64 + ty * 4;
        }
        const float* Wr = W + r0 * C_;

        float acc[4][4];
        #pragma unroll
        for (int r = 0; r < 4; r++) {
            float bb = bias[r0 + r];
            acc[r][0] = bb; acc[r][1] = bb; acc[r][2] = bb; acc[r][3] = bb;
        }

        #pragma unroll 4
        for (int c = 0; c < C_; c++) {
            float4 xv = xs4[c * 16 + tx];
            float w0 = Wr[c], w1 = Wr[C_ + c], w2 = Wr[2 * C_ + c], w3 = Wr[3 * C_ + c];
            acc[0][0] += w0 * xv.x; acc[0][1] += w0 * xv.y; acc[0][2] += w0 * xv.z; acc[0][3] += w0 * xv.w;
            acc[1][0] += w1 * xv.x; acc[1][1] += w1 * xv.y; acc[1][2] += w1 * xv.z; acc[1][3] += w1 * xv.w;
            acc[2][0] += w2 * xv.x; acc[2][1] += w2 * xv.y; acc[2][2] += w2 * xv.z; acc[2][3] += w2 * xv.w;
            acc[3][0] += w3 * xv.x; acc[3][1] += w3 * xv.y; acc[3][2] += w3 * xv.z; acc[3][3] += w3 * xv.w;
        }

        #pragma unroll
        for (int cc = 0; cc < 4; cc++) {
            int n = n0 + tx * 4 + cc;
            float4 val = make_float4(acc[0][cc], acc[1][cc], acc[2][cc], acc[3][cc]);
            if (rb == 0) {
                float* dst = (ty < 8) ? g_q : g_k;
                *(float4*)(dst + ((size_t)b * N_ + n) * CQK + r0) = val;
            } else {
                *(float4*)(g_v + ((size_t)b * N_ + n) * C_ + r0) = val;
            }
        }
    }
}

// ---------------- Kernel 2: fused flash attention ----------------
// grid (N/64, B), 256 threads = 8 warps. Warp ty owns query rows qy..qy+7.
// Lane owns v-dims [lane*8, lane*8+8) and S columns {lane, lane+32}.
__global__ __launch_bounds__(256, 2) void attn_kernel()
{
    __shared__ float Qs[64 * 32];    // [q][d]
    __shared__ float Kst[32 * 64];   // [d][j]  (transposed -> conflict-free lane reads)
    __shared__ float Ss[64 * 64];    // [q][j]  P values (warp-private rows)

    const int b    = blockIdx.y;
    const int n0   = blockIdx.x * 64;
    const int tid  = threadIdx.x;
    const int lane = tid & 31;
    const int ty   = tid >> 5;
    const int qy   = ty * 8;

    // load Q tile (coalesced)
    {
        const float4* q4 = (const float4*)(g_q + ((size_t)b * N_ + n0) * CQK);
        float4* Qs4 = (float4*)Qs;
        for (int i = tid; i < 64 * 8; i += 256) Qs4[i] = q4[i];
    }

    u64 O2[8][4];
    float m[8], l[8];
    #pragma unroll
    for (int q = 0; q < 8; q++) {
        m[q] = -CUDART_INF_F; l[q] = 0.f;
        O2[q][0] = 0ull; O2[q][1] = 0ull; O2[q][2] = 0ull; O2[q][3] = 0ull;
    }

    for (int jt = 0; jt < 64; jt++) {
        const int j0 = jt * 64;

        __syncthreads();   // previous iteration done with Kst (and Qs write on iter 0)
        // load K tile transposed: Kst[d][j]
        const float* kg = g_k + ((size_t)b * N_ + j0) * CQK;
        for (int i = tid; i < 2048; i += 256) {
            int d = i >> 6, j = i & 63;
            Kst[d * 64 + j] = kg[(size_t)j * CQK + d];
        }
        __syncthreads();

        // S = Q K^T : lane computes columns {lane, lane+32} for 8 rows
        float s0[8], s1[8];
        #pragma unroll
        for (int q = 0; q < 8; q++) { s0[q] = 0.f; s1[q] = 0.f; }
        #pragma unroll
        for (int d = 0; d < 32; d++) {
            float k0 = Kst[d * 64 + lane];
            float k1 = Kst[d * 64 + lane + 32];
            #pragma unroll
            for (int q = 0; q < 8; q++) {
                float qv = Qs[(qy + q) * 32 + d];   // broadcast
                s0[q] += qv * k0;
                s1[q] += qv * k1;
            }
        }

        // online softmax per row (warp-collective, all lanes converge on m/l)
        #pragma unroll
        for (int q = 0; q < 8; q++) {
            float mx = fmaxf(s0[q], s1[q]);
            mx = fmaxf(mx, __shfl_xor_sync(0xffffffffu, mx, 16));
            mx = fmaxf(mx, __shfl_xor_sync(0xffffffffu, mx, 8));
            mx = fmaxf(mx, __shfl_xor_sync(0xffffffffu, mx, 4));
            mx = fmaxf(mx, __shfl_xor_sync(0xffffffffu, mx, 2));
            mx = fmaxf(mx, __shfl_xor_sync(0xffffffffu, mx, 1));
            if (mx > m[q]) {                        // uniform branch (mx, m warp-uniform)
                float alpha = __expf(m[q] - mx);    // first tile: exp(-inf) = 0
                l[q] *= alpha;
                u64 ap = pack2(alpha);
                O2[q][0] = mul2(O2[q][0], ap);
                O2[q][1] = mul2(O2[q][1], ap);
                O2[q][2] = mul2(O2[q][2], ap);
                O2[q][3] = mul2(O2[q][3], ap);
                m[q] = mx;
            }
            float p0 = __expf(s0[q] - m[q]);
            float p1 = __expf(s1[q] - m[q]);
            float ps = p0 + p1;
            ps += __shfl_xor_sync(0xffffffffu, ps, 16);
            ps += __shfl_xor_sync(0xffffffffu, ps, 8);
            ps += __shfl_xor_sync(0xffffffffu, ps, 4);
            ps += __shfl_xor_sync(0xffffffffu, ps, 2);
            ps += __shfl_xor_sync(0xffffffffu, ps, 1);
            l[q] += ps;
            Ss[(qy + q) * 64 + lane]      = p0;
            Ss[(qy + q) * 64 + lane + 32] = p1;
        }
        __syncwarp();

        // PV: O[q][cv] += P[q][j] * V[j][cv], packed f32x2 FFMA2
        const u64* vb = (const u64*)(g_v + ((size_t)b * N_ + j0) * C_ + lane * 8);
        #pragma unroll 2
        for (int j = 0; j < 64; j++) {
            const ulonglong2* vp = (const ulonglong2*)(vb + (size_t)j * (C_ / 2));
            ulonglong2 va = vp[0];
            ulonglong2 vc = vp[1];
            #pragma unroll
            for (int q = 0; q < 8; q++) {
                u64 pp = pack2(Ss[(qy + q) * 64 + j]);   // broadcast LDS
                ffma2(O2[q][0], pp, va.x);
                ffma2(O2[q][1], pp, va.y);
                ffma2(O2[q][2], pp, vc.x);
                ffma2(O2[q][3], pp, vc.y);
            }
        }
    }

    // epilogue: normalize and write O (token-major, coalesced)
    #pragma unroll
    for (int q = 0; q < 8; q++) {
        float inv = 1.0f / l[q];
        float2 a0 = unpack2(O2[q][0]);
        float2 a1 = unpack2(O2[q][1]);
        float2 a2 = unpack2(O2[q][2]);
        float2 a3 = unpack2(O2[q][3]);
        float4* dst = (float4*)(g_o + ((size_t)b * N_ + n0 + qy + q) * C_ + lane * 8);
        dst[0] = make_float4(a0.x * inv, a0.y * inv, a1.x * inv, a1.y * inv);
        dst[1] = make_float4(a2.x * inv, a2.y * inv, a3.x * inv, a3.y * inv);
    }
}

// ---------------- Kernel 3: transpose + gamma*o + x ----------------
// grid (N/32, C/32, B), block (32, 8)
__global__ __launch_bounds__(256) void epi_kernel(
    const float* __restrict__ x, const float* __restrict__ gamma,
    float* __restrict__ out)
{
    __shared__ float tile[32][33];
    const int b  = blockIdx.z;
    const int n0 = blockIdx.x * 32;
    const int c0 = blockIdx.y * 32;
    const int tx = threadIdx.x, ty = threadIdx.y;
    const float g = gamma[0];

    #pragma unroll
    for (int i = ty; i < 32; i += 8)
        tile[i][tx] = g_o[((size_t)b * N_ + n0 + i) * C_ + c0 + tx];
    __syncthreads();
    #pragma unroll
    for (int i = ty; i < 32; i += 8) {
        size_t oidx = ((size_t)b * C_ + c0 + i) * N_ + n0 + tx;
        out[oidx] = g * tile[tx][i] + x[oidx];
    }
}

// ---------------- launch ----------------
extern "C" void kernel_launch(void* const* d_in, const int* in_sizes, int n_in,
                              void* d_out, int out_size)
{
    const float* x     = (const float*)d_in[0];
    const float* Wq    = (const float*)d_in[1];
    const float* bq    = (const float*)d_in[2];
    const float* Wk    = (const float*)d_in[3];
    const float* bk    = (const float*)d_in[4];
    const float* Wv    = (const float*)d_in[5];
    const float* bv    = (const float*)d_in[6];
    const float* gamma = (const float*)d_in[7];
    float* out = (float*)d_out;

    cudaFuncSetAttribute(proj_kernel, cudaFuncAttributeMaxDynamicSharedMemorySize, 65536);

    proj_kernel<<<dim3(N_ / 64, B_), 256, 65536>>>(x, Wq, bq, Wk, bk, Wv, bv);
    attn_kernel<<<dim3(N_ / 64, B_), 256>>>();
    epi_kernel<<<dim3(N_ / 32, C_ / 32, B_), dim3(32, 8)>>>(x, gamma, out);
}

// round 8
// speedup vs baseline: 2.5076x; 2.5076x over previous
#include <cuda_runtime.h>
#include <cstdint>
#include <math_constants.h>

#define B_   8
#define C_   256
#define N_   4096
#define CQK  32
#define QT   128     // queries per CTA (attn)
#define JT   64      // keys per j-tile

// Scratch (device globals: allocation-free rule)
__device__ float g_q[(size_t)B_ * N_ * CQK];          // [b][n][32]
__device__ float g_k[(size_t)B_ * N_ * CQK];          // [b][n][32]
__device__ float g_v[(size_t)B_ * N_ * C_];           // [b][n][256]  (token-major)
__device__ float g_o[(size_t)B_ * N_ * C_];           // [b][n][256]  (token-major)

// ---------------- smem layout for attn (float offsets) ----------------
#define VBUF   16640          // 64*260
#define KBUF   2304           // 64*36
#define V0_OFF 0
#define K0_OFF (2*VBUF)                  // 33280
#define P_OFF  (K0_OFF + 2*KBUF)         // 37888
#define PSTR   68
#define PWARP  (16*PSTR)                 // 1088
#define ATTN_SMEM_FLOATS (P_OFF + 8*PWARP)   // 46592 floats = 186368 B

// ---------------- mma / cp.async helpers ----------------
__device__ __forceinline__ void mma_tf32(float& d0, float& d1, float& d2, float& d3,
                                         unsigned a0, unsigned a1, unsigned a2, unsigned a3,
                                         unsigned b0, unsigned b1)
{
    asm volatile("mma.sync.aligned.m16n8k8.row.col.f32.tf32.tf32.f32 "
                 "{%0,%1,%2,%3}, {%4,%5,%6,%7}, {%8,%9}, {%0,%1,%2,%3};\n"
                 : "+f"(d0), "+f"(d1), "+f"(d2), "+f"(d3)
                 : "r"(a0), "r"(a1), "r"(a2), "r"(a3), "r"(b0), "r"(b1));
}
__device__ __forceinline__ void cpa16(unsigned dst, const float* src) {
    asm volatile("cp.async.cg.shared.global [%0], [%1], 16;\n" :: "r"(dst), "l"(src));
}
__device__ __forceinline__ void cpa_commit() { asm volatile("cp.async.commit_group;\n"); }
template<int NN> __device__ __forceinline__ void cpa_wait() {
    asm volatile("cp.async.wait_group %0;\n" :: "n"(NN));
}

// ---------------- Kernel 1: q/k/v projections (vectorized W loads) ----------------
__global__ __launch_bounds__(256) void proj_kernel(
    const float* __restrict__ x,
    const float* __restrict__ Wq, const float* __restrict__ bq,
    const float* __restrict__ Wk, const float* __restrict__ bk,
    const float* __restrict__ Wv, const float* __restrict__ bv)
{
    extern __shared__ float xs[];               // [256][64]
    float4* xs4 = (float4*)xs;
    const int b   = blockIdx.y;
    const int n0  = blockIdx.x * 64;
    const int tid = threadIdx.x;
    const int tx  = tid & 15;
    const int ty  = tid >> 4;

    const float4* x4 = (const float4*)(x + ((size_t)b * C_) * N_ + n0);
    for (int i = tid; i < C_ * 16; i += 256) {
        int c = i >> 4, t4 = i & 15;
        xs4[c * 16 + t4] = x4[(size_t)c * (N_ / 4) + t4];
    }
    __syncthreads();

    #pragma unroll 1
    for (int rb = 0; rb < 5; rb++) {
        const float* W; const float* bias; int r0;
        if (rb == 0) {
            if (ty < 8) { W = Wq; bias = bq; r0 = ty * 4; }
            else        { W = Wk; bias = bk; r0 = (ty - 8) * 4; }
        } else {
            W = Wv; bias = bv; r0 = (rb - 1) * 64 + ty * 4;
        }
        const float* Wr = W + r0 * C_;

        float acc[4][4];
        #pragma unroll
        for (int r = 0; r < 4; r++) {
            float bb = bias[r0 + r];
            acc[r][0] = bb; acc[r][1] = bb; acc[r][2] = bb; acc[r][3] = bb;
        }

        // c in blocks of 4: one LDG.128 per W row per block (weights contiguous in c)
        #pragma unroll 2
        for (int c = 0; c < C_; c += 4) {
            float4 wr0 = *(const float4*)&Wr[c];
            float4 wr1 = *(const float4*)&Wr[C_ + c];
            float4 wr2 = *(const float4*)&Wr[2 * C_ + c];
            float4 wr3 = *(const float4*)&Wr[3 * C_ + c];
            const float w0s[4] = {wr0.x, wr0.y, wr0.z, wr0.w};
            const float w1s[4] = {wr1.x, wr1.y, wr1.z, wr1.w};
            const float w2s[4] = {wr2.x, wr2.y, wr2.z, wr2.w};
            const float w3s[4] = {wr3.x, wr3.y, wr3.z, wr3.w};
            #pragma unroll
            for (int cc = 0; cc < 4; cc++) {
                float4 xv = xs4[(c + cc) * 16 + tx];
                float w0 = w0s[cc], w1 = w1s[cc], w2 = w2s[cc], w3 = w3s[cc];
                acc[0][0] += w0 * xv.x; acc[0][1] += w0 * xv.y; acc[0][2] += w0 * xv.z; acc[0][3] += w0 * xv.w;
                acc[1][0] += w1 * xv.x; acc[1][1] += w1 * xv.y; acc[1][2] += w1 * xv.z; acc[1][3] += w1 * xv.w;
                acc[2][0] += w2 * xv.x; acc[2][1] += w2 * xv.y; acc[2][2] += w2 * xv.z; acc[2][3] += w2 * xv.w;
                acc[3][0] += w3 * xv.x; acc[3][1] += w3 * xv.y; acc[3][2] += w3 * xv.z; acc[3][3] += w3 * xv.w;
            }
        }

        #pragma unroll
        for (int cc = 0; cc < 4; cc++) {
            int n = n0 + tx * 4 + cc;
            float4 val = make_float4(acc[0][cc], acc[1][cc], acc[2][cc], acc[3][cc]);
            if (rb == 0) {
                float* dst = (ty < 8) ? g_q : g_k;
                *(float4*)(dst + ((size_t)b * N_ + n) * CQK + r0) = val;
            } else {
                *(float4*)(g_v + ((size_t)b * N_ + n) * C_ + r0) = val;
            }
        }
    }
}

// ---------------- attn tile loader (cp.async double-buffer) ----------------
__device__ __forceinline__ void load_tiles(float* sm, int b, int j0, int buf, int tid)
{
    // V tile [64][256] -> padded [64][260]
    unsigned vbase = (unsigned)__cvta_generic_to_shared(sm + V0_OFF + buf * VBUF);
    const float* vsrc = g_v + ((size_t)b * N_ + j0) * C_;
    #pragma unroll
    for (int i = 0; i < 16; i++) {
        int idx = tid + i * 256;          // 0..4095 float4s
        int row = idx >> 6, c4 = idx & 63;
        cpa16(vbase + (unsigned)(row * 260 + c4 * 4) * 4u, vsrc + (size_t)row * C_ + c4 * 4);
    }
    // K tile [64][32] -> padded [64][36]
    unsigned kbase = (unsigned)__cvta_generic_to_shared(sm + K0_OFF + buf * KBUF);
    const float* ksrc = g_k + ((size_t)b * N_ + j0) * CQK;
    #pragma unroll
    for (int i = 0; i < 2; i++) {
        int idx = tid + i * 256;          // 0..511 float4s
        int row = idx >> 3, c4 = idx & 7;
        cpa16(kbase + (unsigned)(row * 36 + c4 * 4) * 4u, ksrc + (size_t)row * CQK + c4 * 4);
    }
}

// ---------------- Kernel 2: flash attention via tf32 mma.sync ----------------
// grid (N/128, B), 256 threads = 8 warps; warp w owns query rows [w*16, w*16+16).
__global__ __launch_bounds__(256, 1) void attn_kernel()
{
    extern __shared__ float sm[];
    const int b    = blockIdx.y;
    const int n0   = blockIdx.x * QT;
    const int tid  = threadIdx.x;
    const int lane = tid & 31;
    const int w    = tid >> 5;
    const int qr   = lane >> 2;      // 0..7
    const int qc   = lane & 3;       // 0..3

    // Q fragments (A of m16n8k8), raw f32 bits as tf32, resident for whole kernel
    unsigned qa[4][4];
    {
        const float* qb = g_q + ((size_t)b * N_ + n0 + w * 16) * CQK;
        #pragma unroll
        for (int kt = 0; kt < 4; kt++) {
            qa[kt][0] = __float_as_uint(qb[(size_t)qr       * CQK + kt * 8 + qc]);
            qa[kt][1] = __float_as_uint(qb[(size_t)(qr + 8) * CQK + kt * 8 + qc]);
            qa[kt][2] = __float_as_uint(qb[(size_t)qr       * CQK + kt * 8 + qc + 4]);
            qa[kt][3] = __float_as_uint(qb[(size_t)(qr + 8) * CQK + kt * 8 + qc + 4]);
        }
    }

    float acc[32][4];                 // O strip 16x256 per warp
    #pragma unroll
    for (int nt = 0; nt < 32; nt++) {
        acc[nt][0] = 0.f; acc[nt][1] = 0.f; acc[nt][2] = 0.f; acc[nt][3] = 0.f;
    }
    float m0 = -CUDART_INF_F, m1 = -CUDART_INF_F, l0 = 0.f, l1 = 0.f;

    load_tiles(sm, b, 0, 0, tid);
    cpa_commit();

    float* Pw = sm + P_OFF + w * PWARP;

    for (int jt = 0; jt < N_ / JT; jt++) {
        const int buf = jt & 1;
        if (jt + 1 < N_ / JT) {
            load_tiles(sm, b, (jt + 1) * JT, (jt + 1) & 1, tid);
            cpa_commit();
            cpa_wait<1>();
        } else {
            cpa_wait<0>();
        }
        __syncthreads();

        const float* Ks = sm + K0_OFF + buf * KBUF;
        const float* Vs = sm + V0_OFF + buf * VBUF;

        // ---- S = Q K^T (16x64 strip) ----
        float sacc[8][4];
        #pragma unroll
        for (int nt = 0; nt < 8; nt++) {
            sacc[nt][0] = 0.f; sacc[nt][1] = 0.f; sacc[nt][2] = 0.f; sacc[nt][3] = 0.f;
        }
        #pragma unroll
        for (int kt = 0; kt < 4; kt++) {
            #pragma unroll
            for (int nt = 0; nt < 8; nt++) {
                unsigned kb0 = __float_as_uint(Ks[(nt * 8 + qr) * 36 + kt * 8 + qc]);
                unsigned kb1 = __float_as_uint(Ks[(nt * 8 + qr) * 36 + kt * 8 + qc + 4]);
                mma_tf32(sacc[nt][0], sacc[nt][1], sacc[nt][2], sacc[nt][3],
                         qa[kt][0], qa[kt][1], qa[kt][2], qa[kt][3], kb0, kb1);
            }
        }

        // ---- online softmax (rows qr and qr+8) ----
        float mx0 = -CUDART_INF_F, mx1 = -CUDART_INF_F;
        #pragma unroll
        for (int nt = 0; nt < 8; nt++) {
            mx0 = fmaxf(mx0, fmaxf(sacc[nt][0], sacc[nt][1]));
            mx1 = fmaxf(mx1, fmaxf(sacc[nt][2], sacc[nt][3]));
        }
        mx0 = fmaxf(mx0, __shfl_xor_sync(0xffffffffu, mx0, 1));
        mx0 = fmaxf(mx0, __shfl_xor_sync(0xffffffffu, mx0, 2));
        mx1 = fmaxf(mx1, __shfl_xor_sync(0xffffffffu, mx1, 1));
        mx1 = fmaxf(mx1, __shfl_xor_sync(0xffffffffu, mx1, 2));

        float nm0 = fmaxf(m0, mx0), nm1 = fmaxf(m1, mx1);
        float al0 = __expf(m0 - nm0), al1 = __expf(m1 - nm1);
        m0 = nm0; m1 = nm1;

        float s0 = 0.f, s1 = 0.f;
        #pragma unroll
        for (int nt = 0; nt < 8; nt++) {
            float p0 = __expf(sacc[nt][0] - nm0);
            float p1 = __expf(sacc[nt][1] - nm0);
            float p2 = __expf(sacc[nt][2] - nm1);
            float p3 = __expf(sacc[nt][3] - nm1);
            s0 += p0 + p1; s1 += p2 + p3;
            *(float2*)&Pw[qr * PSTR + nt * 8 + 2 * qc]       = make_float2(p0, p1);
            *(float2*)&Pw[(qr + 8) * PSTR + nt * 8 + 2 * qc] = make_float2(p2, p3);
        }
        s0 += __shfl_xor_sync(0xffffffffu, s0, 1);
        s0 += __shfl_xor_sync(0xffffffffu, s0, 2);
        s1 += __shfl_xor_sync(0xffffffffu, s1, 1);
        s1 += __shfl_xor_sync(0xffffffffu, s1, 2);
        l0 = l0 * al0 + s0;
        l1 = l1 * al1 + s1;

        if (__any_sync(0xffffffffu, (al0 != 1.f) || (al1 != 1.f))) {
            #pragma unroll
            for (int nt = 0; nt < 32; nt++) {
                acc[nt][0] *= al0; acc[nt][1] *= al0;
                acc[nt][2] *= al1; acc[nt][3] *= al1;
            }
        }
        __syncwarp();

        // ---- PV: O += P V ----
        #pragma unroll 1
        for (int ks = 0; ks < 8; ks++) {
            unsigned pa0 = __float_as_uint(Pw[qr * PSTR + ks * 8 + qc]);
            unsigned pa1 = __float_as_uint(Pw[(qr + 8) * PSTR + ks * 8 + qc]);
            unsigned pa2 = __float_as_uint(Pw[qr * PSTR + ks * 8 + qc + 4]);
            unsigned pa3 = __float_as_uint(Pw[(qr + 8) * PSTR + ks * 8 + qc + 4]);
            const float* vrow0 = Vs + (ks * 8 + qc) * 260 + qr;
            const float* vrow1 = Vs + (ks * 8 + qc + 4) * 260 + qr;
            #pragma unroll
            for (int nt = 0; nt < 32; nt++) {
                unsigned vb0 = __float_as_uint(vrow0[nt * 8]);
                unsigned vb1 = __float_as_uint(vrow1[nt * 8]);
                mma_tf32(acc[nt][0], acc[nt][1], acc[nt][2], acc[nt][3],
                         pa0, pa1, pa2, pa3, vb0, vb1);
            }
        }
        __syncthreads();   // protect buffers before next-next prefetch overwrites
    }

    // ---- normalize + write O (token-major) ----
    float inv0 = 1.f / l0, inv1 = 1.f / l1;
    float* ob = g_o + ((size_t)b * N_ + n0 + w * 16) * C_;
    #pragma unroll
    for (int nt = 0; nt < 32; nt++) {
        *(float2*)&ob[(size_t)qr * C_ + nt * 8 + 2 * qc] =
            make_float2(acc[nt][0] * inv0, acc[nt][1] * inv0);
        *(float2*)&ob[(size_t)(qr + 8) * C_ + nt * 8 + 2 * qc] =
            make_float2(acc[nt][2] * inv1, acc[nt][3] * inv1);
    }
}

// ---------------- Kernel 3: transpose + gamma*o + x (unchanged) ----------------
__global__ __launch_bounds__(256) void epi_kernel(
    const float* __restrict__ x, const float* __restrict__ gamma,
    float* __restrict__ out)
{
    __shared__ float tile[32][33];
    const int b  = blockIdx.z;
    const int n0 = blockIdx.x * 32;
    const int c0 = blockIdx.y * 32;
    const int tx = threadIdx.x, ty = threadIdx.y;
    const float g = gamma[0];

    #pragma unroll
    for (int i = ty; i < 32; i += 8)
        tile[i][tx] = g_o[((size_t)b * N_ + n0 + i) * C_ + c0 + tx];
    __syncthreads();
    #pragma unroll
    for (int i = ty; i < 32; i += 8) {
        size_t oidx = ((size_t)b * C_ + c0 + i) * N_ + n0 + tx;
        out[oidx] = g * tile[tx][i] + x[oidx];
    }
}

// ---------------- launch ----------------
extern "C" void kernel_launch(void* const* d_in, const int* in_sizes, int n_in,
                              void* d_out, int out_size)
{
    const float* x     = (const float*)d_in[0];
    const float* Wq    = (const float*)d_in[1];
    const float* bq    = (const float*)d_in[2];
    const float* Wk    = (const float*)d_in[3];
    const float* bk    = (const float*)d_in[4];
    const float* Wv    = (const float*)d_in[5];
    const float* bv    = (const float*)d_in[6];
    const float* gamma = (const float*)d_in[7];
    float* out = (float*)d_out;

    cudaFuncSetAttribute(proj_kernel, cudaFuncAttributeMaxDynamicSharedMemorySize, 65536);
    cudaFuncSetAttribute(attn_kernel, cudaFuncAttributeMaxDynamicSharedMemorySize,
                         ATTN_SMEM_FLOATS * sizeof(float));

    proj_kernel<<<dim3(N_ / 64, B_), 256, 65536>>>(x, Wq, bq, Wk, bk, Wv, bv);
    attn_kernel<<<dim3(N_ / QT, B_), 256, ATTN_SMEM_FLOATS * sizeof(float)>>>();
    epi_kernel<<<dim3(N_ / 32, C_ / 32, B_), dim3(32, 8)>>>(x, gamma, out);
}

// round 10
// speedup vs baseline: 4.2738x; 1.7044x over previous
#include <cuda_runtime.h>
#include <cstdint>
#include <math_constants.h>

#define B_   8
#define C_   256
#define N_   4096
#define CQK  32
#define QT   128     // queries per CTA (attn)
#define JT   64      // keys per j-tile

typedef unsigned long long u64;

// Scratch (device globals: allocation-free rule)
__device__ float    g_q [(size_t)B_ * N_ * CQK];       // [b][n][32] fp32
__device__ float    g_k [(size_t)B_ * N_ * CQK];       // [b][n][32] fp32
__device__ unsigned g_vb[(size_t)B_ * C_ * N_ / 2];    // [b][c][n] bf16 (channel-major, u32 = 2 tokens)
__device__ float    g_o [(size_t)B_ * N_ * C_];        // [b][n][256] fp32 token-major

// ---------------- attn smem layout (byte offsets) ----------------
#define VT0    0
#define VTBUF  36864            // 256 rows(c) * 144 B (72 bf16, padded)
#define K0_OFF (2*VTBUF)        // 73728
#define KBUF   9216             // 64 rows(j) * 144 B (36 f32, padded)
#define P_OFF  (K0_OFF + 2*KBUF)  // 92160
#define PWARPB 2304             // 16 rows(q) * 144 B (72 bf16, padded)
#define ATTN_SMEM_BYTES (P_OFF + 8*PWARPB)   // 110592

// ---------------- helpers ----------------
__device__ __forceinline__ void mma_tf32(float& d0, float& d1, float& d2, float& d3,
                                         unsigned a0, unsigned a1, unsigned a2, unsigned a3,
                                         unsigned b0, unsigned b1)
{
    asm volatile("mma.sync.aligned.m16n8k8.row.col.f32.tf32.tf32.f32 "
                 "{%0,%1,%2,%3}, {%4,%5,%6,%7}, {%8,%9}, {%0,%1,%2,%3};\n"
                 : "+f"(d0), "+f"(d1), "+f"(d2), "+f"(d3)
                 : "r"(a0), "r"(a1), "r"(a2), "r"(a3), "r"(b0), "r"(b1));
}
__device__ __forceinline__ void mma_bf16(float& d0, float& d1, float& d2, float& d3,
                                         unsigned a0, unsigned a1, unsigned a2, unsigned a3,
                                         unsigned b0, unsigned b1)
{
    asm volatile("mma.sync.aligned.m16n8k16.row.col.f32.bf16.bf16.f32 "
                 "{%0,%1,%2,%3}, {%4,%5,%6,%7}, {%8,%9}, {%0,%1,%2,%3};\n"
                 : "+f"(d0), "+f"(d1), "+f"(d2), "+f"(d3)
                 : "r"(a0), "r"(a1), "r"(a2), "r"(a3), "r"(b0), "r"(b1));
}
__device__ __forceinline__ unsigned bf16x2_of(float hi, float lo) {
    unsigned r;
    asm("cvt.rn.bf16x2.f32 %0, %1, %2;" : "=r"(r) : "f"(hi), "f"(lo));
    return r;
}
__device__ __forceinline__ void cpa16(unsigned dst, const void* src) {
    asm volatile("cp.async.cg.shared.global [%0], [%1], 16;\n" :: "r"(dst), "l"(src));
}
__device__ __forceinline__ void cpa_commit() { asm volatile("cp.async.commit_group;\n"); }
template<int NN> __device__ __forceinline__ void cpa_wait() {
    asm volatile("cp.async.wait_group %0;\n" :: "n"(NN));
}
__device__ __forceinline__ void ffma2(u64& d, u64 a, u64 b) {
    asm("fma.rn.f32x2 %0, %1, %2, %0;" : "+l"(d) : "l"(a), "l"(b));
}
__device__ __forceinline__ u64 pack2f(float v) {
    u64 r; unsigned u = __float_as_uint(v);
    asm("mov.b64 %0, {%1, %1};" : "=l"(r) : "r"(u)); return r;
}
__device__ __forceinline__ float2 unpk2(u64 v) {
    float2 r; asm("mov.b64 {%0, %1}, %2;" : "=f"(r.x), "=f"(r.y) : "l"(v)); return r;
}

// ---------------- Kernel 1: q/k/v projections (FFMA2 + bf16 V store) ----------------
// grid (N/64, B), 256 threads, 64KB smem: x tile [256][64]
__global__ __launch_bounds__(256) void proj_kernel(
    const float* __restrict__ x,
    const float* __restrict__ Wq, const float* __restrict__ bq,
    const float* __restrict__ Wk, const float* __restrict__ bk,
    const float* __restrict__ Wv, const float* __restrict__ bv)
{
    extern __shared__ float xs[];               // [256][64]
    float4* xs4 = (float4*)xs;
    const int b   = blockIdx.y;
    const int n0  = blockIdx.x * 64;
    const int tid = threadIdx.x;
    const int tx  = tid & 15;                   // token group: tokens tx*4..tx*4+3
    const int ty  = tid >> 4;

    const float4* x4 = (const float4*)(x + ((size_t)b * C_) * N_ + n0);
    for (int i = tid; i < C_ * 16; i += 256) {
        int c = i >> 4, t4 = i & 15;
        xs4[c * 16 + t4] = x4[(size_t)c * (N_ / 4) + t4];
    }
    __syncthreads();

    #pragma unroll 1
    for (int rb = 0; rb < 5; rb++) {
        const float* W; const float* bias; int r0;
        if (rb == 0) {
            if (ty < 8) { W = Wq; bias = bq; r0 = ty * 4; }
            else        { W = Wk; bias = bk; r0 = (ty - 8) * 4; }
        } else {
            W = Wv; bias = bv; r0 = (rb - 1) * 64 + ty * 4;
        }
        const float* Wr = W + r0 * C_;

        u64 acc2[4][2];                       // [row r][token-pair]
        #pragma unroll
        for (int r = 0; r < 4; r++) {
            u64 bb = pack2f(bias[r0 + r]);
            acc2[r][0] = bb; acc2[r][1] = bb;
        }

        #pragma unroll 2
        for (int c = 0; c < C_; c += 4) {
            float4 wr0 = *(const float4*)&Wr[c];
            float4 wr1 = *(const float4*)&Wr[C_ + c];
            float4 wr2 = *(const float4*)&Wr[2 * C_ + c];
            float4 wr3 = *(const float4*)&Wr[3 * C_ + c];
            const float w0s[4] = {wr0.x, wr0.y, wr0.z, wr0.w};
            const float w1s[4] = {wr1.x, wr1.y, wr1.z, wr1.w};
            const float w2s[4] = {wr2.x, wr2.y, wr2.z, wr2.w};
            const float w3s[4] = {wr3.x, wr3.y, wr3.z, wr3.w};
            #pragma unroll
            for (int cc = 0; cc < 4; cc++) {
                ulonglong2 xv2 = *(const ulonglong2*)&xs4[(c + cc) * 16 + tx];
                u64 w0p = pack2f(w0s[cc]);
                u64 w1p = pack2f(w1s[cc]);
                u64 w2p = pack2f(w2s[cc]);
                u64 w3p = pack2f(w3s[cc]);
                ffma2(acc2[0][0], w0p, xv2.x); ffma2(acc2[0][1], w0p, xv2.y);
                ffma2(acc2[1][0], w1p, xv2.x); ffma2(acc2[1][1], w1p, xv2.y);
                ffma2(acc2[2][0], w2p, xv2.x); ffma2(acc2[2][1], w2p, xv2.y);
                ffma2(acc2[3][0], w3p, xv2.x); ffma2(acc2[3][1], w3p, xv2.y);
            }
        }

        float acc[4][4];
        #pragma unroll
        for (int r = 0; r < 4; r++) {
            float2 p0 = unpk2(acc2[r][0]);
            float2 p1 = unpk2(acc2[r][1]);
            acc[r][0] = p0.x; acc[r][1] = p0.y; acc[r][2] = p1.x; acc[r][3] = p1.y;
        }

        if (rb == 0) {
            float* dst = (ty < 8) ? g_q : g_k;
            #pragma unroll
            for (int cc = 0; cc < 4; cc++) {
                int n = n0 + tx * 4 + cc;
                *(float4*)(dst + ((size_t)b * N_ + n) * CQK + r0) =
                    make_float4(acc[0][cc], acc[1][cc], acc[2][cc], acc[3][cc]);
            }
        } else {
            // V: bf16, channel-major [b][c][n]; 4 consecutive tokens -> 8 B store
            #pragma unroll
            for (int r = 0; r < 4; r++) {
                unsigned lo = bf16x2_of(acc[r][1], acc[r][0]);   // tokens +0,+1 (lo=token0)
                unsigned hi = bf16x2_of(acc[r][3], acc[r][2]);   // tokens +2,+3
                size_t idx = ((size_t)b * C_ + r0 + r) * N_ + n0 + tx * 4;   // bf16 units, %4==0
                *(uint2*)(g_vb + (idx >> 1)) = make_uint2(lo, hi);
            }
        }
    }
}

// ---------------- attn tile loader (cp.async double-buffer) ----------------
__device__ __forceinline__ void load_tiles(char* smc, int b, int j0, int buf, int tid)
{
    // V^T tile: 256 channel-rows x 64 bf16 (128 B) -> padded 144 B rows
    unsigned vbase = (unsigned)__cvta_generic_to_shared(smc + VT0 + buf * VTBUF);
    const unsigned* vsrc = g_vb + (((size_t)b * C_) * N_ + j0) / 2;
    #pragma unroll
    for (int i = 0; i < 8; i++) {
        int idx = tid + i * 256;              // 0..2047 16B-chunks
        int c = idx >> 3, col8 = idx & 7;     // channel row, 8-bf16 chunk
        cpa16(vbase + (unsigned)(c * 144 + col8 * 16),
              vsrc + (size_t)c * (N_ / 2) + col8 * 4);
    }
    // K tile [64][32] f32 -> padded [64][36] (144 B rows)
    unsigned kbase = (unsigned)__cvta_generic_to_shared(smc + K0_OFF + buf * KBUF);
    const float* ksrc = g_k + ((size_t)b * N_ + j0) * CQK;
    #pragma unroll
    for (int i = 0; i < 2; i++) {
        int idx = tid + i * 256;              // 0..511 16B-chunks
        int row = idx >> 3, c4 = idx & 7;
        cpa16(kbase + (unsigned)(row * 144 + c4 * 16), ksrc + (size_t)row * CQK + c4 * 4);
    }
}

// ---------------- Kernel 2: flash attention (tf32 QK^T, bf16 PV) ----------------
// grid (N/128, B), 256 threads = 8 warps; warp w owns query rows [w*16, w*16+16).
__global__ __launch_bounds__(256, 1) void attn_kernel()
{
    extern __shared__ char smc[];
    const int b    = blockIdx.y;
    const int n0   = blockIdx.x * QT;
    const int tid  = threadIdx.x;
    const int lane = tid & 31;
    const int w    = tid >> 5;
    const int qr   = lane >> 2;      // 0..7
    const int qc   = lane & 3;       // 0..3

    // Q fragments (A of m16n8k8 tf32), resident for whole kernel
    unsigned qa[4][4];
    {
        const float* qb = g_q + ((size_t)b * N_ + n0 + w * 16) * CQK;
        #pragma unroll
        for (int kt = 0; kt < 4; kt++) {
            qa[kt][0] = __float_as_uint(qb[(size_t)qr       * CQK + kt * 8 + qc]);
            qa[kt][1] = __float_as_uint(qb[(size_t)(qr + 8) * CQK + kt * 8 + qc]);
            qa[kt][2] = __float_as_uint(qb[(size_t)qr       * CQK + kt * 8 + qc + 4]);
            qa[kt][3] = __float_as_uint(qb[(size_t)(qr + 8) * CQK + kt * 8 + qc + 4]);
        }
    }

    float acc[32][4];                 // O strip 16x256 per warp
    #pragma unroll
    for (int nt = 0; nt < 32; nt++) {
        acc[nt][0] = 0.f; acc[nt][1] = 0.f; acc[nt][2] = 0.f; acc[nt][3] = 0.f;
    }
    float m0 = -CUDART_INF_F, m1 = -CUDART_INF_F, l0 = 0.f, l1 = 0.f;

    load_tiles(smc, b, 0, 0, tid);
    cpa_commit();

    char* Pb = smc + P_OFF + w * PWARPB;

    for (int jt = 0; jt < N_ / JT; jt++) {
        const int buf = jt & 1;
        if (jt + 1 < N_ / JT) {
            load_tiles(smc, b, (jt + 1) * JT, (jt + 1) & 1, tid);
            cpa_commit();
            cpa_wait<1>();
        } else {
            cpa_wait<0>();
        }
        __syncthreads();

        const float* Ks = (const float*)(smc + K0_OFF + buf * KBUF);
        const char*  Vt = smc + VT0 + buf * VTBUF;

        // ---- S = Q K^T (16x64 strip), tf32 ----
        float sacc[8][4];
        #pragma unroll
        for (int nt = 0; nt < 8; nt++) {
            sacc[nt][0] = 0.f; sacc[nt][1] = 0.f; sacc[nt][2] = 0.f; sacc[nt][3] = 0.f;
        }
        #pragma unroll
        for (int kt = 0; kt < 4; kt++) {
            #pragma unroll
            for (int nt = 0; nt < 8; nt++) {
                unsigned kb0 = __float_as_uint(Ks[(nt * 8 + qr) * 36 + kt * 8 + qc]);
                unsigned kb1 = __float_as_uint(Ks[(nt * 8 + qr) * 36 + kt * 8 + qc + 4]);
                mma_tf32(sacc[nt][0], sacc[nt][1], sacc[nt][2], sacc[nt][3],
                         qa[kt][0], qa[kt][1], qa[kt][2], qa[kt][3], kb0, kb1);
            }
        }

        // ---- online softmax (rows qr and qr+8); P stored as bf16x2 ----
        float mx0 = -CUDART_INF_F, mx1 = -CUDART_INF_F;
        #pragma unroll
        for (int nt = 0; nt < 8; nt++) {
            mx0 = fmaxf(mx0, fmaxf(sacc[nt][0], sacc[nt][1]));
            mx1 = fmaxf(mx1, fmaxf(sacc[nt][2], sacc[nt][3]));
        }
        mx0 = fmaxf(mx0, __shfl_xor_sync(0xffffffffu, mx0, 1));
        mx0 = fmaxf(mx0, __shfl_xor_sync(0xffffffffu, mx0, 2));
        mx1 = fmaxf(mx1, __shfl_xor_sync(0xffffffffu, mx1, 1));
        mx1 = fmaxf(mx1, __shfl_xor_sync(0xffffffffu, mx1, 2));

        float nm0 = fmaxf(m0, mx0), nm1 = fmaxf(m1, mx1);
        float al0 = __expf(m0 - nm0), al1 = __expf(m1 - nm1);
        m0 = nm0; m1 = nm1;

        float s0 = 0.f, s1 = 0.f;
        #pragma unroll
        for (int nt = 0; nt < 8; nt++) {
            float p0 = __expf(sacc[nt][0] - nm0);
            float p1 = __expf(sacc[nt][1] - nm0);
            float p2 = __expf(sacc[nt][2] - nm1);
            float p3 = __expf(sacc[nt][3] - nm1);
            s0 += p0 + p1; s1 += p2 + p3;
            *(unsigned*)(Pb + qr * 144 + nt * 16 + qc * 4)       = bf16x2_of(p1, p0);
            *(unsigned*)(Pb + (qr + 8) * 144 + nt * 16 + qc * 4) = bf16x2_of(p3, p2);
        }
        s0 += __shfl_xor_sync(0xffffffffu, s0, 1);
        s0 += __shfl_xor_sync(0xffffffffu, s0, 2);
        s1 += __shfl_xor_sync(0xffffffffu, s1, 1);
        s1 += __shfl_xor_sync(0xffffffffu, s1, 2);
        l0 = l0 * al0 + s0;
        l1 = l1 * al1 + s1;

        if (__any_sync(0xffffffffu, (al0 != 1.f) || (al1 != 1.f))) {
            #pragma unroll
            for (int nt = 0; nt < 32; nt++) {
                acc[nt][0] *= al0; acc[nt][1] *= al0;
                acc[nt][2] *= al1; acc[nt][3] *= al1;
            }
        }
        __syncwarp();

        // ---- PV: O += P V, bf16 m16n8k16 (k = 16 keys per step) ----
        #pragma unroll 1
        for (int ks = 0; ks < 4; ks++) {
            unsigned pa0 = *(const unsigned*)(Pb + qr * 144 + ks * 32 + qc * 4);
            unsigned pa1 = *(const unsigned*)(Pb + (qr + 8) * 144 + ks * 32 + qc * 4);
            unsigned pa2 = *(const unsigned*)(Pb + qr * 144 + ks * 32 + qc * 4 + 16);
            unsigned pa3 = *(const unsigned*)(Pb + (qr + 8) * 144 + ks * 32 + qc * 4 + 16);
            const char* vrow = Vt + qr * 144 + ks * 32 + qc * 4;
            #pragma unroll
            for (int nt = 0; nt < 32; nt++) {
                unsigned vb0 = *(const unsigned*)(vrow + nt * (8 * 144));
                unsigned vb1 = *(const unsigned*)(vrow + nt * (8 * 144) + 16);
                mma_bf16(acc[nt][0], acc[nt][1], acc[nt][2], acc[nt][3],
                         pa0, pa1, pa2, pa3, vb0, vb1);
            }
        }
        __syncthreads();   // protect buffers before next-next prefetch overwrites
    }

    // ---- normalize + write O (token-major) ----
    float inv0 = 1.f / l0, inv1 = 1.f / l1;
    float* ob = g_o + ((size_t)b * N_ + n0 + w * 16) * C_;
    #pragma unroll
    for (int nt = 0; nt < 32; nt++) {
        *(float2*)&ob[(size_t)qr * C_ + nt * 8 + 2 * qc] =
            make_float2(acc[nt][0] * inv0, acc[nt][1] * inv0);
        *(float2*)&ob[(size_t)(qr + 8) * C_ + nt * 8 + 2 * qc] =
            make_float2(acc[nt][2] * inv1, acc[nt][3] * inv1);
    }
}

// ---------------- Kernel 3: transpose + gamma*o + x ----------------
__global__ __launch_bounds__(256) void epi_kernel(
    const float* __restrict__ x, const float* __restrict__ gamma,
    float* __restrict__ out)
{
    __shared__ float tile[32][33];
    const int b  = blockIdx.z;
    const int n0 = blockIdx.x * 32;
    const int c0 = blockIdx.y * 32;
    const int tx = threadIdx.x, ty = threadIdx.y;
    const float g = gamma[0];

    #pragma unroll
    for (int i = ty; i < 32; i += 8)
        tile[i][tx] = g_o[((size_t)b * N_ + n0 + i) * C_ + c0 + tx];
    __syncthreads();
    #pragma unroll
    for (int i = ty; i < 32; i += 8) {
        size_t oidx = ((size_t)b * C_ + c0 + i) * N_ + n0 + tx;
        out[oidx] = g * tile[tx][i] + x[oidx];
    }
}

// ---------------- launch ----------------
extern "C" void kernel_launch(void* const* d_in, const int* in_sizes, int n_in,
                              void* d_out, int out_size)
{
    const float* x     = (const float*)d_in[0];
    const float* Wq    = (const float*)d_in[1];
    const float* bq    = (const float*)d_in[2];
    const float* Wk    = (const float*)d_in[3];
    const float* bk    = (const float*)d_in[4];
    const float* Wv    = (const float*)d_in[5];
    const float* bv    = (const float*)d_in[6];
    const float* gamma = (const float*)d_in[7];
    float* out = (float*)d_out;

    cudaFuncSetAttribute(proj_kernel, cudaFuncAttributeMaxDynamicSharedMemorySize, 65536);
    cudaFuncSetAttribute(attn_kernel, cudaFuncAttributeMaxDynamicSharedMemorySize,
                         ATTN_SMEM_BYTES);

    proj_kernel<<<dim3(N_ / 64, B_), 256, 65536>>>(x, Wq, bq, Wk, bk, Wv, bv);
    attn_kernel<<<dim3(N_ / QT, B_), 256, ATTN_SMEM_BYTES>>>();
    epi_kernel<<<dim3(N_ / 32, C_ / 32, B_), dim3(32, 8)>>>(x, gamma, out);
}